// round 1
// baseline (speedup 1.0000x reference)
#include <cuda_runtime.h>
#include <math.h>

#define S_LEN   4096
#define H_DIM   2048
#define NHEADS  16
#define HDIM    128
#define QKV_N   (3 * H_DIM)

// Scratch (no cudaMalloc allowed)
__device__ float g_qkv[S_LEN * QKV_N];    // [4096, 6144]
__device__ float g_attn[S_LEN * H_DIM];   // [4096, 2048]

// ---------------------------------------------------------------------------
// C[M,N] = A[M,K] * B[N,K]^T   (both A and B row-major, K-contiguous)
// 128x128 block tile, BK=8, 256 threads, 8x8 microtile per thread.
// ---------------------------------------------------------------------------
#define BM 128
#define BN 128
#define BKD 8

__global__ __launch_bounds__(256, 2) void gemm_abt(
    const float* __restrict__ A, const float* __restrict__ B,
    float* __restrict__ C, int M, int N, int K)
{
    __shared__ float As[BKD][BM];
    __shared__ float Bs[BKD][BN];

    const int tid = threadIdx.x;
    const int tx = tid & 15;      // 0..15  (N microtile)
    const int ty = tid >> 4;      // 0..15  (M microtile)
    const int mBase = blockIdx.y * BM;
    const int nBase = blockIdx.x * BN;

    // global->shared loader indices: each thread loads one float4 from A and B
    const int lr = tid >> 1;          // 0..127
    const int lk = (tid & 1) * 4;     // 0 or 4
    const float* Aptr = A + (long)(mBase + lr) * K + lk;
    const float* Bptr = B + (long)(nBase + lr) * K + lk;

    float acc[8][8];
#pragma unroll
    for (int i = 0; i < 8; ++i)
#pragma unroll
        for (int j = 0; j < 8; ++j) acc[i][j] = 0.0f;

    for (int k0 = 0; k0 < K; k0 += BKD) {
        float4 a = *(const float4*)(Aptr + k0);
        float4 b = *(const float4*)(Bptr + k0);
        As[lk + 0][lr] = a.x; As[lk + 1][lr] = a.y;
        As[lk + 2][lr] = a.z; As[lk + 3][lr] = a.w;
        Bs[lk + 0][lr] = b.x; Bs[lk + 1][lr] = b.y;
        Bs[lk + 2][lr] = b.z; Bs[lk + 3][lr] = b.w;
        __syncthreads();

#pragma unroll
        for (int kk = 0; kk < BKD; ++kk) {
            float ra[8], rb[8];
            *(float4*)(ra)     = *(const float4*)&As[kk][ty * 4];
            *(float4*)(ra + 4) = *(const float4*)&As[kk][ty * 4 + 64];
            *(float4*)(rb)     = *(const float4*)&Bs[kk][tx * 4];
            *(float4*)(rb + 4) = *(const float4*)&Bs[kk][tx * 4 + 64];
#pragma unroll
            for (int i = 0; i < 8; ++i)
#pragma unroll
                for (int j = 0; j < 8; ++j)
                    acc[i][j] += ra[i] * rb[j];
        }
        __syncthreads();
    }

    // epilogue
#pragma unroll
    for (int i = 0; i < 8; ++i) {
        int r = mBase + ty * 4 + ((i < 4) ? i : (64 + i - 4));
        float4 v0 = make_float4(acc[i][0], acc[i][1], acc[i][2], acc[i][3]);
        float4 v1 = make_float4(acc[i][4], acc[i][5], acc[i][6], acc[i][7]);
        *(float4*)&C[(long)r * N + nBase + tx * 4]      = v0;
        *(float4*)&C[(long)r * N + nBase + 64 + tx * 4] = v1;
    }
}

// ---------------------------------------------------------------------------
// Flash attention, fp32. One block = (head, 64 q-rows). 256 threads.
// Tiles in smem are row-major with stride 132 (conflict-free LDS.128 via
// interleaved fragments: rows r = ty + 16*ii, cols c = tx + 16*jj).
// K and V share one smem buffer (serialized by syncthreads).
// ---------------------------------------------------------------------------
#define BQ 64
#define BKV 64
#define TSTRIDE 132                 // 128 + 4, multiple of 4 for float4 align
#define PSTRIDE 68                  // 64 + 4

#define FLASH_SMEM_FLOATS (2 * BQ * TSTRIDE + BKV * PSTRIDE)
#define FLASH_SMEM_BYTES  (FLASH_SMEM_FLOATS * 4)

__global__ __launch_bounds__(256, 2) void flash_attn(
    const float* __restrict__ qkv, float* __restrict__ out)
{
    extern __shared__ float sm[];
    float* Qs  = sm;                         // [64][132]
    float* KVs = sm + BQ * TSTRIDE;          // [64][132]
    float* Ps  = sm + 2 * BQ * TSTRIDE;      // [64][68]  (transposed: [j][r])

    const int tid = threadIdx.x;
    const int tx = tid & 15;
    const int ty = tid >> 4;
    const int head = blockIdx.y;
    const int q0 = blockIdx.x * BQ;
    const int qoff = head * HDIM;
    const int koff = H_DIM + head * HDIM;
    const int voff = 2 * H_DIM + head * HDIM;

    // load Q tile [64][128] row-major (coalesced)
#pragma unroll
    for (int it = 0; it < 8; ++it) {
        int idx = tid + it * 256;          // 0..2047
        int s  = idx >> 5;                 // 0..63
        int d4 = (idx & 31) * 4;           // 0..124
        *(float4*)&Qs[s * TSTRIDE + d4] =
            *(const float4*)&qkv[(long)(q0 + s) * QKV_N + qoff + d4];
    }

    float m_i[4], l_i[4], o_acc[4][8];
#pragma unroll
    for (int ii = 0; ii < 4; ++ii) {
        m_i[ii] = -1e30f; l_i[ii] = 0.0f;
#pragma unroll
        for (int c = 0; c < 8; ++c) o_acc[ii][c] = 0.0f;
    }
    const float scale = 0.08838834764831845f;   // 1/sqrt(128)

    for (int kt = 0; kt < S_LEN / BKV; ++kt) {
        const int k0 = kt * BKV;
        __syncthreads();
        // load K tile
#pragma unroll
        for (int it = 0; it < 8; ++it) {
            int idx = tid + it * 256;
            int s = idx >> 5, d4 = (idx & 31) * 4;
            *(float4*)&KVs[s * TSTRIDE + d4] =
                *(const float4*)&qkv[(long)(k0 + s) * QKV_N + koff + d4];
        }
        __syncthreads();

        // S = Q K^T  (4x4 fragment per thread, rows ty+16*ii, cols tx+16*jj)
        float sc[4][4];
#pragma unroll
        for (int ii = 0; ii < 4; ++ii)
#pragma unroll
            for (int jj = 0; jj < 4; ++jj) sc[ii][jj] = 0.0f;

        for (int d = 0; d < HDIM; d += 4) {
            float4 qv[4], kv[4];
#pragma unroll
            for (int ii = 0; ii < 4; ++ii)
                qv[ii] = *(const float4*)&Qs[(ty + 16 * ii) * TSTRIDE + d];
#pragma unroll
            for (int jj = 0; jj < 4; ++jj)
                kv[jj] = *(const float4*)&KVs[(tx + 16 * jj) * TSTRIDE + d];
#pragma unroll
            for (int ii = 0; ii < 4; ++ii)
#pragma unroll
                for (int jj = 0; jj < 4; ++jj) {
                    sc[ii][jj] += qv[ii].x * kv[jj].x;
                    sc[ii][jj] += qv[ii].y * kv[jj].y;
                    sc[ii][jj] += qv[ii].z * kv[jj].z;
                    sc[ii][jj] += qv[ii].w * kv[jj].w;
                }
        }

        // online softmax update per owned row
#pragma unroll
        for (int ii = 0; ii < 4; ++ii) {
#pragma unroll
            for (int jj = 0; jj < 4; ++jj) sc[ii][jj] *= scale;
            float rm = fmaxf(fmaxf(sc[ii][0], sc[ii][1]),
                             fmaxf(sc[ii][2], sc[ii][3]));
#pragma unroll
            for (int msk = 1; msk < 16; msk <<= 1)
                rm = fmaxf(rm, __shfl_xor_sync(0xffffffffu, rm, msk));
            float mn = fmaxf(m_i[ii], rm);
            float corr = __expf(m_i[ii] - mn);
            m_i[ii] = mn;
            float rs = 0.0f;
#pragma unroll
            for (int jj = 0; jj < 4; ++jj) {
                float p = __expf(sc[ii][jj] - mn);
                Ps[(tx + 16 * jj) * PSTRIDE + ty + 16 * ii] = p;
                rs += p;
            }
#pragma unroll
            for (int msk = 1; msk < 16; msk <<= 1)
                rs += __shfl_xor_sync(0xffffffffu, rs, msk);
            l_i[ii] = l_i[ii] * corr + rs;
#pragma unroll
            for (int c = 0; c < 8; ++c) o_acc[ii][c] *= corr;
        }
        __syncthreads();     // all S reads of KVs + Ps writes done

        // load V tile into same buffer
#pragma unroll
        for (int it = 0; it < 8; ++it) {
            int idx = tid + it * 256;
            int s = idx >> 5, d4 = (idx & 31) * 4;
            *(float4*)&KVs[s * TSTRIDE + d4] =
                *(const float4*)&qkv[(long)(k0 + s) * QKV_N + voff + d4];
        }
        __syncthreads();

        // O += P V   (O cols: tx*4..+3 and 64+tx*4..+3)
        for (int j = 0; j < BKV; ++j) {
            float4 v0 = *(const float4*)&KVs[j * TSTRIDE + tx * 4];
            float4 v1 = *(const float4*)&KVs[j * TSTRIDE + 64 + tx * 4];
#pragma unroll
            for (int ii = 0; ii < 4; ++ii) {
                float p = Ps[j * PSTRIDE + ty + 16 * ii];
                o_acc[ii][0] += p * v0.x; o_acc[ii][1] += p * v0.y;
                o_acc[ii][2] += p * v0.z; o_acc[ii][3] += p * v0.w;
                o_acc[ii][4] += p * v1.x; o_acc[ii][5] += p * v1.y;
                o_acc[ii][6] += p * v1.z; o_acc[ii][7] += p * v1.w;
            }
        }
    }

    // epilogue: divide by (l + 1e-8), write [s, head*128 + d]
#pragma unroll
    for (int ii = 0; ii < 4; ++ii) {
        float inv = 1.0f / (l_i[ii] + 1e-8f);
        int r = q0 + ty + 16 * ii;
        float4 w0 = make_float4(o_acc[ii][0] * inv, o_acc[ii][1] * inv,
                                o_acc[ii][2] * inv, o_acc[ii][3] * inv);
        float4 w1 = make_float4(o_acc[ii][4] * inv, o_acc[ii][5] * inv,
                                o_acc[ii][6] * inv, o_acc[ii][7] * inv);
        *(float4*)&out[(long)r * H_DIM + head * HDIM + tx * 4]      = w0;
        *(float4*)&out[(long)r * H_DIM + head * HDIM + 64 + tx * 4] = w1;
    }
}

// ---------------------------------------------------------------------------
extern "C" void kernel_launch(void* const* d_in, const int* in_sizes, int n_in,
                              void* d_out, int out_size)
{
    const float* x     = (const float*)d_in[0];   // [4096, 2048]
    const float* w_qkv = (const float*)d_in[1];   // [6144, 2048]
    const float* w_out = (const float*)d_in[2];   // [2048, 2048]
    float* out = (float*)d_out;                   // [4096, 2048]

    float* qkv_ptr = nullptr;
    float* attn_ptr = nullptr;
    cudaGetSymbolAddress((void**)&qkv_ptr, g_qkv);
    cudaGetSymbolAddress((void**)&attn_ptr, g_attn);

    cudaFuncSetAttribute(flash_attn,
                         cudaFuncAttributeMaxDynamicSharedMemorySize,
                         FLASH_SMEM_BYTES);

    // 1) qkv = x @ w_qkv^T
    gemm_abt<<<dim3(QKV_N / BN, S_LEN / BM), 256>>>(
        x, w_qkv, qkv_ptr, S_LEN, QKV_N, H_DIM);

    // 2) flash attention
    flash_attn<<<dim3(S_LEN / BQ, NHEADS), 256, FLASH_SMEM_BYTES>>>(
        qkv_ptr, attn_ptr);

    // 3) out = attn @ w_out^T
    gemm_abt<<<dim3(H_DIM / BN, S_LEN / BM), 256>>>(
        attn_ptr, w_out, out, S_LEN, H_DIM, H_DIM);
}

// round 3
// speedup vs baseline: 1.2338x; 1.2338x over previous
#include <cuda_runtime.h>
#include <cuda_bf16.h>
#include <mma.h>
#include <cstdint>
#include <math.h>

using namespace nvcuda;

#define S_LEN   4096
#define H_DIM   2048
#define NHEADS  16
#define HDIM    128
#define QKV_N   (3 * H_DIM)

// ---------------------------------------------------------------------------
// Scratch (no cudaMalloc allowed)
// ---------------------------------------------------------------------------
__device__ __align__(16) float g_qkv[S_LEN * QKV_N];     // [4096, 6144]
__device__ __align__(16) float g_attn[S_LEN * H_DIM];    // [4096, 2048]
__device__ __align__(16) __nv_bfloat16 g_x_hi[S_LEN * H_DIM];
__device__ __align__(16) __nv_bfloat16 g_x_lo[S_LEN * H_DIM];
__device__ __align__(16) __nv_bfloat16 g_wq_hi[QKV_N * H_DIM];
__device__ __align__(16) __nv_bfloat16 g_wq_lo[QKV_N * H_DIM];
__device__ __align__(16) __nv_bfloat16 g_wo_hi[H_DIM * H_DIM];
__device__ __align__(16) __nv_bfloat16 g_wo_lo[H_DIM * H_DIM];
__device__ __align__(16) __nv_bfloat16 g_a_hi[S_LEN * H_DIM];
__device__ __align__(16) __nv_bfloat16 g_a_lo[S_LEN * H_DIM];

// ---------------------------------------------------------------------------
// fp32 -> (hi, lo) bf16 split, 4-wide
// ---------------------------------------------------------------------------
__global__ void cvt_split4(const float4* __restrict__ in,
                           __nv_bfloat162* __restrict__ hi,
                           __nv_bfloat162* __restrict__ lo, int n4)
{
    int i = blockIdx.x * 256 + threadIdx.x;
    if (i >= n4) return;
    float4 v = in[i];
    __nv_bfloat16 hx = __float2bfloat16(v.x);
    __nv_bfloat16 hy = __float2bfloat16(v.y);
    __nv_bfloat16 hz = __float2bfloat16(v.z);
    __nv_bfloat16 hw = __float2bfloat16(v.w);
    hi[2 * i]     = __halves2bfloat162(hx, hy);
    hi[2 * i + 1] = __halves2bfloat162(hz, hw);
    __nv_bfloat16 lx = __float2bfloat16(v.x - __bfloat162float(hx));
    __nv_bfloat16 ly = __float2bfloat16(v.y - __bfloat162float(hy));
    __nv_bfloat16 lz = __float2bfloat16(v.z - __bfloat162float(hz));
    __nv_bfloat16 lw = __float2bfloat16(v.w - __bfloat162float(hw));
    lo[2 * i]     = __halves2bfloat162(lx, ly);
    lo[2 * i + 1] = __halves2bfloat162(lz, lw);
}

// ---------------------------------------------------------------------------
// wmma bf16x3 GEMM: C[M,N] = A[M,K] * B[N,K]^T  (fp32 via hi/lo bf16 split)
// 128x128x32 CTA tile, 256 threads (8 warps, 4 along M x 2 along N),
// each warp 32x64 = 2x4 wmma 16x16x16 tiles, fp32 accumulators.
// ---------------------------------------------------------------------------
#define GBM 128
#define GBN 128
#define GBK 32
#define TSTR 40   // smem row stride in bf16 elems (80B, 16B-aligned, conflict-light)

__global__ __launch_bounds__(256, 1) void gemm_wmma(
    const __nv_bfloat16* __restrict__ Ahi, const __nv_bfloat16* __restrict__ Alo,
    const __nv_bfloat16* __restrict__ Bhi, const __nv_bfloat16* __restrict__ Blo,
    float* __restrict__ C, int M, int N, int K)
{
    __shared__ __nv_bfloat16 sAh[GBM][TSTR];
    __shared__ __nv_bfloat16 sAl[GBM][TSTR];
    __shared__ __nv_bfloat16 sBh[GBN][TSTR];
    __shared__ __nv_bfloat16 sBl[GBN][TSTR];

    const int tid = threadIdx.x;
    const int wid = tid >> 5;
    const int warp_m = wid & 3;       // 0..3
    const int warp_n = wid >> 2;      // 0..1
    const int mBase = blockIdx.y * GBM;
    const int nBase = blockIdx.x * GBN;
    const int wm = warp_m * 32;       // warp row offset in tile
    const int wn = warp_n * 64;       // warp col offset in tile

    wmma::fragment<wmma::accumulator, 16, 16, 16, float> acc[2][4];
#pragma unroll
    for (int i = 0; i < 2; ++i)
#pragma unroll
        for (int j = 0; j < 4; ++j) wmma::fill_fragment(acc[i][j], 0.0f);

    // loader: 128 rows x 32 cols bf16 per tile = 512 float4; 2 per thread/tile
    const int lr0 = tid >> 2;              // row for i=0 pass: 0..63 twice pattern
    for (int k0 = 0; k0 < K; k0 += GBK) {
        __syncthreads();
#pragma unroll
        for (int i = 0; i < 2; ++i) {
            int idx = tid + i * 256;       // 0..511
            int r = idx >> 2;              // 0..127
            int c = (idx & 3) * 8;         // bf16 col 0,8,16,24
            *(float4*)&sAh[r][c] = *(const float4*)&Ahi[(long)(mBase + r) * K + k0 + c];
            *(float4*)&sAl[r][c] = *(const float4*)&Alo[(long)(mBase + r) * K + k0 + c];
            *(float4*)&sBh[r][c] = *(const float4*)&Bhi[(long)(nBase + r) * K + k0 + c];
            *(float4*)&sBl[r][c] = *(const float4*)&Blo[(long)(nBase + r) * K + k0 + c];
        }
        __syncthreads();

#pragma unroll
        for (int kk = 0; kk < GBK; kk += 16) {
            wmma::fragment<wmma::matrix_a, 16, 16, 16, __nv_bfloat16, wmma::row_major> ah[2], al[2];
            wmma::fragment<wmma::matrix_b, 16, 16, 16, __nv_bfloat16, wmma::col_major> bh[4], bl[4];
#pragma unroll
            for (int i = 0; i < 2; ++i) {
                wmma::load_matrix_sync(ah[i], &sAh[wm + i * 16][kk], TSTR);
                wmma::load_matrix_sync(al[i], &sAl[wm + i * 16][kk], TSTR);
            }
#pragma unroll
            for (int j = 0; j < 4; ++j) {
                wmma::load_matrix_sync(bh[j], &sBh[wn + j * 16][kk], TSTR);
                wmma::load_matrix_sync(bl[j], &sBl[wn + j * 16][kk], TSTR);
            }
#pragma unroll
            for (int i = 0; i < 2; ++i)
#pragma unroll
                for (int j = 0; j < 4; ++j) {
                    wmma::mma_sync(acc[i][j], ah[i], bh[j], acc[i][j]);
                    wmma::mma_sync(acc[i][j], ah[i], bl[j], acc[i][j]);
                    wmma::mma_sync(acc[i][j], al[i], bh[j], acc[i][j]);
                }
        }
    }

    // epilogue: direct global store of fp32 accumulators
#pragma unroll
    for (int i = 0; i < 2; ++i)
#pragma unroll
        for (int j = 0; j < 4; ++j) {
            float* cp = C + (long)(mBase + wm + i * 16) * N + nBase + wn + j * 16;
            wmma::store_matrix_sync(cp, acc[i][j], N, wmma::mem_row_major);
        }
}

// ---------------------------------------------------------------------------
// Flash attention, fp32 SIMT (unchanged)
// ---------------------------------------------------------------------------
#define BQ 64
#define BKV 64
#define TSTRIDE 132
#define PSTRIDE 68
#define FLASH_SMEM_FLOATS (2 * BQ * TSTRIDE + BKV * PSTRIDE)
#define FLASH_SMEM_BYTES  (FLASH_SMEM_FLOATS * 4)

__global__ __launch_bounds__(256, 2) void flash_attn(
    const float* __restrict__ qkv, float* __restrict__ out)
{
    extern __shared__ float sm[];
    float* Qs  = sm;
    float* KVs = sm + BQ * TSTRIDE;
    float* Ps  = sm + 2 * BQ * TSTRIDE;

    const int tid = threadIdx.x;
    const int tx = tid & 15;
    const int ty = tid >> 4;
    const int head = blockIdx.y;
    const int q0 = blockIdx.x * BQ;
    const int qoff = head * HDIM;
    const int koff = H_DIM + head * HDIM;
    const int voff = 2 * H_DIM + head * HDIM;

#pragma unroll
    for (int it = 0; it < 8; ++it) {
        int idx = tid + it * 256;
        int s  = idx >> 5;
        int d4 = (idx & 31) * 4;
        *(float4*)&Qs[s * TSTRIDE + d4] =
            *(const float4*)&qkv[(long)(q0 + s) * QKV_N + qoff + d4];
    }

    float m_i[4], l_i[4], o_acc[4][8];
#pragma unroll
    for (int ii = 0; ii < 4; ++ii) {
        m_i[ii] = -1e30f; l_i[ii] = 0.0f;
#pragma unroll
        for (int c = 0; c < 8; ++c) o_acc[ii][c] = 0.0f;
    }
    const float scale = 0.08838834764831845f;

    for (int kt = 0; kt < S_LEN / BKV; ++kt) {
        const int k0 = kt * BKV;
        __syncthreads();
#pragma unroll
        for (int it = 0; it < 8; ++it) {
            int idx = tid + it * 256;
            int s = idx >> 5, d4 = (idx & 31) * 4;
            *(float4*)&KVs[s * TSTRIDE + d4] =
                *(const float4*)&qkv[(long)(k0 + s) * QKV_N + koff + d4];
        }
        __syncthreads();

        float sc[4][4];
#pragma unroll
        for (int ii = 0; ii < 4; ++ii)
#pragma unroll
            for (int jj = 0; jj < 4; ++jj) sc[ii][jj] = 0.0f;

        for (int d = 0; d < HDIM; d += 4) {
            float4 qv[4], kv[4];
#pragma unroll
            for (int ii = 0; ii < 4; ++ii)
                qv[ii] = *(const float4*)&Qs[(ty + 16 * ii) * TSTRIDE + d];
#pragma unroll
            for (int jj = 0; jj < 4; ++jj)
                kv[jj] = *(const float4*)&KVs[(tx + 16 * jj) * TSTRIDE + d];
#pragma unroll
            for (int ii = 0; ii < 4; ++ii)
#pragma unroll
                for (int jj = 0; jj < 4; ++jj) {
                    sc[ii][jj] += qv[ii].x * kv[jj].x;
                    sc[ii][jj] += qv[ii].y * kv[jj].y;
                    sc[ii][jj] += qv[ii].z * kv[jj].z;
                    sc[ii][jj] += qv[ii].w * kv[jj].w;
                }
        }

#pragma unroll
        for (int ii = 0; ii < 4; ++ii) {
#pragma unroll
            for (int jj = 0; jj < 4; ++jj) sc[ii][jj] *= scale;
            float rm = fmaxf(fmaxf(sc[ii][0], sc[ii][1]),
                             fmaxf(sc[ii][2], sc[ii][3]));
#pragma unroll
            for (int msk = 1; msk < 16; msk <<= 1)
                rm = fmaxf(rm, __shfl_xor_sync(0xffffffffu, rm, msk));
            float mn = fmaxf(m_i[ii], rm);
            float corr = __expf(m_i[ii] - mn);
            m_i[ii] = mn;
            float rs = 0.0f;
#pragma unroll
            for (int jj = 0; jj < 4; ++jj) {
                float p = __expf(sc[ii][jj] - mn);
                Ps[(tx + 16 * jj) * PSTRIDE + ty + 16 * ii] = p;
                rs += p;
            }
#pragma unroll
            for (int msk = 1; msk < 16; msk <<= 1)
                rs += __shfl_xor_sync(0xffffffffu, rs, msk);
            l_i[ii] = l_i[ii] * corr + rs;
#pragma unroll
            for (int c = 0; c < 8; ++c) o_acc[ii][c] *= corr;
        }
        __syncthreads();

#pragma unroll
        for (int it = 0; it < 8; ++it) {
            int idx = tid + it * 256;
            int s = idx >> 5, d4 = (idx & 31) * 4;
            *(float4*)&KVs[s * TSTRIDE + d4] =
                *(const float4*)&qkv[(long)(k0 + s) * QKV_N + voff + d4];
        }
        __syncthreads();

        for (int j = 0; j < BKV; ++j) {
            float4 v0 = *(const float4*)&KVs[j * TSTRIDE + tx * 4];
            float4 v1 = *(const float4*)&KVs[j * TSTRIDE + 64 + tx * 4];
#pragma unroll
            for (int ii = 0; ii < 4; ++ii) {
                float p = Ps[j * PSTRIDE + ty + 16 * ii];
                o_acc[ii][0] += p * v0.x; o_acc[ii][1] += p * v0.y;
                o_acc[ii][2] += p * v0.z; o_acc[ii][3] += p * v0.w;
                o_acc[ii][4] += p * v1.x; o_acc[ii][5] += p * v1.y;
                o_acc[ii][6] += p * v1.z; o_acc[ii][7] += p * v1.w;
            }
        }
    }

#pragma unroll
    for (int ii = 0; ii < 4; ++ii) {
        float inv = 1.0f / (l_i[ii] + 1e-8f);
        int r = q0 + ty + 16 * ii;
        float4 w0 = make_float4(o_acc[ii][0] * inv, o_acc[ii][1] * inv,
                                o_acc[ii][2] * inv, o_acc[ii][3] * inv);
        float4 w1 = make_float4(o_acc[ii][4] * inv, o_acc[ii][5] * inv,
                                o_acc[ii][6] * inv, o_acc[ii][7] * inv);
        *(float4*)&out[(long)r * H_DIM + head * HDIM + tx * 4]      = w0;
        *(float4*)&out[(long)r * H_DIM + head * HDIM + 64 + tx * 4] = w1;
    }
}

// ---------------------------------------------------------------------------
extern "C" void kernel_launch(void* const* d_in, const int* in_sizes, int n_in,
                              void* d_out, int out_size)
{
    const float* x     = (const float*)d_in[0];   // [4096, 2048]
    const float* w_qkv = (const float*)d_in[1];   // [6144, 2048]
    const float* w_out = (const float*)d_in[2];   // [2048, 2048]
    float* out = (float*)d_out;                   // [4096, 2048]

    float *qkv_ptr, *attn_ptr;
    __nv_bfloat16 *x_hi, *x_lo, *wq_hi, *wq_lo, *wo_hi, *wo_lo, *a_hi, *a_lo;
    cudaGetSymbolAddress((void**)&qkv_ptr, g_qkv);
    cudaGetSymbolAddress((void**)&attn_ptr, g_attn);
    cudaGetSymbolAddress((void**)&x_hi, g_x_hi);
    cudaGetSymbolAddress((void**)&x_lo, g_x_lo);
    cudaGetSymbolAddress((void**)&wq_hi, g_wq_hi);
    cudaGetSymbolAddress((void**)&wq_lo, g_wq_lo);
    cudaGetSymbolAddress((void**)&wo_hi, g_wo_hi);
    cudaGetSymbolAddress((void**)&wo_lo, g_wo_lo);
    cudaGetSymbolAddress((void**)&a_hi, g_a_hi);
    cudaGetSymbolAddress((void**)&a_lo, g_a_lo);

    cudaFuncSetAttribute(flash_attn,
                         cudaFuncAttributeMaxDynamicSharedMemorySize,
                         FLASH_SMEM_BYTES);

    // 0) split inputs to bf16 hi/lo
    {
        int n4 = (S_LEN * H_DIM) / 4;
        cvt_split4<<<(n4 + 255) / 256, 256>>>(
            (const float4*)x, (__nv_bfloat162*)x_hi, (__nv_bfloat162*)x_lo, n4);
        n4 = (QKV_N * H_DIM) / 4;
        cvt_split4<<<(n4 + 255) / 256, 256>>>(
            (const float4*)w_qkv, (__nv_bfloat162*)wq_hi, (__nv_bfloat162*)wq_lo, n4);
        n4 = (H_DIM * H_DIM) / 4;
        cvt_split4<<<(n4 + 255) / 256, 256>>>(
            (const float4*)w_out, (__nv_bfloat162*)wo_hi, (__nv_bfloat162*)wo_lo, n4);
    }

    // 1) qkv = x @ w_qkv^T  (wmma bf16x3)
    gemm_wmma<<<dim3(QKV_N / GBN, S_LEN / GBM), 256>>>(
        x_hi, x_lo, wq_hi, wq_lo, qkv_ptr, S_LEN, QKV_N, H_DIM);

    // 2) flash attention (fp32)
    flash_attn<<<dim3(S_LEN / BQ, NHEADS), 256, FLASH_SMEM_BYTES>>>(
        qkv_ptr, attn_ptr);

    // 3) split attn, then out = attn @ w_out^T (wmma bf16x3)
    {
        int n4 = (S_LEN * H_DIM) / 4;
        cvt_split4<<<(n4 + 255) / 256, 256>>>(
            (const float4*)attn_ptr, (__nv_bfloat162*)a_hi, (__nv_bfloat162*)a_lo, n4);
    }
    gemm_wmma<<<dim3(H_DIM / GBN, S_LEN / GBM), 256>>>(
        a_hi, a_lo, wo_hi, wo_lo, out, S_LEN, H_DIM, H_DIM);
}